// round 3
// baseline (speedup 1.0000x reference)
#include <cuda_runtime.h>
#include <cstdint>

#define HIDDEN 128
#define NCLS 16
#define MAXN 100000
#define MAXE 3200000

// ---------------- device scratch (no allocations allowed) ----------------
__device__ float g_deg [MAXN];
__device__ float g_dinv[MAXN];
__device__ int   g_cnt [MAXN];            // in-degree counts (excl self loop)
__device__ int   g_off [MAXN + 1];        // CSR offsets
__device__ int   g_cur [MAXN];            // placement cursors
__device__ int2  g_csr [MAXE];            // (src row, norm) per edge, grouped by dst
__device__ float g_h1  [(size_t)MAXN * HIDDEN];  // emb @ W1
__device__ float g_x1  [(size_t)MAXN * HIDDEN];  // layer-1 aggregated (pre-relu)
__device__ float g_h2  [(size_t)MAXN * NCLS];    // relu(x1) @ W2
__device__ int   g_is64;

// index loader: edge_index may be int64 (jax x64 on) or int32 (default)
__device__ __forceinline__ long long load_idx(const void* ei, long long pos, int is64) {
    if (is64) return ((const long long*)ei)[pos];
    return (long long)((const int*)ei)[pos];
}

// ---------------- dtype detection ----------------
__global__ void detect_kernel(const void* ei, int twoE, int nrows) {
    if (blockIdx.x == 0 && threadIdx.x == 0) {
        const long long* p = (const long long*)ei;
        int n = twoE / 2;
        if (n > 512) n = 512;
        int is64 = 1;
        for (int i = 0; i < n; i++) {
            long long v = p[i];
            if (v < 0 || v >= (long long)nrows) { is64 = 0; break; }
        }
        g_is64 = is64;
    }
}

// ---------------- init: deg=1 (self loop), cnt=0 ----------------
__global__ void init_kernel(int n) {
    int i = blockIdx.x * blockDim.x + threadIdx.x;
    if (i < n) { g_deg[i] = 1.0f; g_cnt[i] = 0; }
}

// ---------------- degree (weighted) + in-degree count ----------------
__global__ void degcnt_kernel(const void* __restrict__ ei, const float* __restrict__ ew, int E) {
    int is64 = g_is64;
    int e = blockIdx.x * blockDim.x + threadIdx.x;
    if (e >= E) return;
    int c = (int)load_idx(ei, (long long)E + e, is64);
    atomicAdd(&g_deg[c], __ldg(ew + e));
    atomicAdd(&g_cnt[c], 1);
}

__global__ void dinv_kernel(int n) {
    int i = blockIdx.x * blockDim.x + threadIdx.x;
    if (i < n) {
        float d = g_deg[i];
        g_dinv[i] = (d > 0.0f) ? rsqrtf(d) : 0.0f;
    }
}

// ---------------- exclusive scan of g_cnt -> g_off (single block, 1024 thr, 4 elem/thr/iter) ----------------
__global__ __launch_bounds__(1024) void scan_kernel(int n) {
    __shared__ int warp_tot[32];
    __shared__ int s_carry;
    int tid = threadIdx.x, lane = tid & 31, wid = tid >> 5;
    if (tid == 0) s_carry = 0;
    __syncthreads();
    for (int base = 0; base < n; base += 4096) {
        int idx = base + tid * 4;
        int a0 = 0, a1 = 0, a2 = 0, a3 = 0;
        if (idx + 3 < n) {
            int4 v = *(const int4*)&g_cnt[idx];
            a0 = v.x; a1 = v.y; a2 = v.z; a3 = v.w;
        } else {
            if (idx + 0 < n) a0 = g_cnt[idx + 0];
            if (idx + 1 < n) a1 = g_cnt[idx + 1];
            if (idx + 2 < n) a2 = g_cnt[idx + 2];
            if (idx + 3 < n) a3 = g_cnt[idx + 3];
        }
        int s = a0 + a1 + a2 + a3;
        int sc = s;                                   // inclusive warp scan
#pragma unroll
        for (int d = 1; d < 32; d <<= 1) {
            int t = __shfl_up_sync(0xFFFFFFFFu, sc, d);
            if (lane >= d) sc += t;
        }
        if (lane == 31) warp_tot[wid] = sc;
        __syncthreads();
        if (wid == 0) {
            int wv = warp_tot[lane];
            int ws = wv;
#pragma unroll
            for (int d = 1; d < 32; d <<= 1) {
                int t = __shfl_up_sync(0xFFFFFFFFu, ws, d);
                if (lane >= d) ws += t;
            }
            warp_tot[lane] = ws - wv;                 // exclusive
        }
        __syncthreads();
        int excl = s_carry + warp_tot[wid] + (sc - s);
        if (idx + 0 < n) g_off[idx + 0] = excl;
        if (idx + 1 < n) g_off[idx + 1] = excl + a0;
        if (idx + 2 < n) g_off[idx + 2] = excl + a0 + a1;
        if (idx + 3 < n) g_off[idx + 3] = excl + a0 + a1 + a2;
        __syncthreads();
        if (tid == 1023) s_carry += warp_tot[31] + sc;
        __syncthreads();
    }
    if (tid == 0) g_off[n] = s_carry;
}

__global__ void cursor_kernel(int n) {
    int i = blockIdx.x * blockDim.x + threadIdx.x;
    if (i < n) g_cur[i] = g_off[i];
}

// ---------------- CSR placement: record (row, norm) grouped by col ----------------
__global__ void place_kernel(const void* __restrict__ ei, const float* __restrict__ ew, int E) {
    int is64 = g_is64;
    int e = blockIdx.x * blockDim.x + threadIdx.x;
    if (e >= E) return;
    int r = (int)load_idx(ei, e, is64);
    int c = (int)load_idx(ei, (long long)E + e, is64);
    float nrm = g_dinv[r] * __ldg(ew + e) * g_dinv[c];
    int pos = atomicAdd(&g_cur[c], 1);
    g_csr[pos] = make_int2(r, __float_as_int(nrm));
}

// ---------------- GEMM1: h1 = emb @ W1 ----------------
__global__ __launch_bounds__(256) void gemm1_kernel(
    const float* __restrict__ emb, const float* __restrict__ W1, int nrows)
{
    __shared__ float sA[64][64];    // 16 KB
    __shared__ float sW[64][128];   // 32 KB
    int tid  = threadIdx.x;
    int warp = tid >> 5, lane = tid & 31;
    int row0 = blockIdx.x * 64;

    float acc[8][4];
#pragma unroll
    for (int r = 0; r < 8; r++)
#pragma unroll
        for (int c = 0; c < 4; c++) acc[r][c] = 0.0f;

    for (int kt = 0; kt < HIDDEN; kt += 64) {
        __syncthreads();
#pragma unroll
        for (int i = 0; i < 4; i++) {
            int idx = tid + i * 256;          // 0..1023
            int r = idx >> 4, c4 = idx & 15;
            int gr = row0 + r;
            float4 v = make_float4(0.f, 0.f, 0.f, 0.f);
            if (gr < nrows)
                v = *(const float4*)(emb + (size_t)gr * HIDDEN + kt + c4 * 4);
            *(float4*)&sA[r][c4 * 4] = v;
        }
#pragma unroll
        for (int i = 0; i < 8; i++) {
            int idx = tid + i * 256;          // 0..2047
            int k = idx >> 5, c4 = idx & 31;
            *(float4*)&sW[k][c4 * 4] =
                *(const float4*)(W1 + (size_t)(kt + k) * HIDDEN + c4 * 4);
        }
        __syncthreads();
#pragma unroll 4
        for (int k = 0; k < 64; k++) {
            float4 wv = *(float4*)&sW[k][lane * 4];
#pragma unroll
            for (int r = 0; r < 8; r++) {
                float a = sA[warp * 8 + r][k];
                acc[r][0] += a * wv.x;
                acc[r][1] += a * wv.y;
                acc[r][2] += a * wv.z;
                acc[r][3] += a * wv.w;
            }
        }
    }
#pragma unroll
    for (int r = 0; r < 8; r++) {
        int gr = row0 + warp * 8 + r;
        if (gr < nrows)
            *(float4*)(g_h1 + (size_t)gr * HIDDEN + lane * 4) =
                make_float4(acc[r][0], acc[r][1], acc[r][2], acc[r][3]);
    }
}

// ---------------- gather1: x1[i] = b1 + dinv_i^2*h1[i] + sum_j nrm_j*h1[row_j]  (1 warp/node) ----------------
__global__ __launch_bounds__(256) void gather1_kernel(const float* __restrict__ b1, int n)
{
    int gw   = (blockIdx.x * 256 + threadIdx.x) >> 5;
    int lane = threadIdx.x & 31;
    if (gw >= n) return;
    int start = g_off[gw], end = g_off[gw + 1];
    float di = g_dinv[gw];
    float s  = di * di;

    float4 hv = ((const float4*)(g_h1 + (size_t)gw * HIDDEN))[lane];
    float4 bb = ((const float4*)b1)[lane];
    float4 acc0 = make_float4(bb.x + s * hv.x, bb.y + s * hv.y,
                              bb.z + s * hv.z, bb.w + s * hv.w);
    float4 acc1 = make_float4(0.f, 0.f, 0.f, 0.f);

    int j = start;
    for (; j + 2 <= end; j += 2) {
        int2 e0 = g_csr[j], e1 = g_csr[j + 1];
        float4 v0 = ((const float4*)(g_h1 + (size_t)e0.x * HIDDEN))[lane];
        float4 v1 = ((const float4*)(g_h1 + (size_t)e1.x * HIDDEN))[lane];
        float n0 = __int_as_float(e0.y), n1 = __int_as_float(e1.y);
        acc0.x += n0 * v0.x; acc0.y += n0 * v0.y; acc0.z += n0 * v0.z; acc0.w += n0 * v0.w;
        acc1.x += n1 * v1.x; acc1.y += n1 * v1.y; acc1.z += n1 * v1.z; acc1.w += n1 * v1.w;
    }
    if (j < end) {
        int2 e0 = g_csr[j];
        float4 v0 = ((const float4*)(g_h1 + (size_t)e0.x * HIDDEN))[lane];
        float n0 = __int_as_float(e0.y);
        acc0.x += n0 * v0.x; acc0.y += n0 * v0.y; acc0.z += n0 * v0.z; acc0.w += n0 * v0.w;
    }
    ((float4*)(g_x1 + (size_t)gw * HIDDEN))[lane] =
        make_float4(acc0.x + acc1.x, acc0.y + acc1.y, acc0.z + acc1.z, acc0.w + acc1.w);
}

// ---------------- GEMM2: h2 = relu(x1) @ W2 ----------------
__global__ __launch_bounds__(256) void gemm2_kernel(const float* __restrict__ W2, int nrows)
{
    __shared__ float sA[64][132];    // padded: conflict-free row access
    __shared__ float sW[128][16];
    int tid  = threadIdx.x;
    int row0 = blockIdx.x * 64;

#pragma unroll
    for (int i = 0; i < 2; i++) {
        int idx = tid + i * 256;
        *(float4*)((float*)sW + idx * 4) = *(const float4*)(W2 + idx * 4);
    }
#pragma unroll
    for (int i = 0; i < 8; i++) {
        int idx = tid + i * 256;          // 0..2047
        int r = idx >> 5, c4 = idx & 31;
        int gr = row0 + r;
        float4 v = make_float4(0.f, 0.f, 0.f, 0.f);
        if (gr < nrows)
            v = *(const float4*)(g_x1 + (size_t)gr * HIDDEN + c4 * 4);
        v.x = fmaxf(v.x, 0.f); v.y = fmaxf(v.y, 0.f);
        v.z = fmaxf(v.z, 0.f); v.w = fmaxf(v.w, 0.f);
        *(float4*)&sA[r][c4 * 4] = v;
    }
    __syncthreads();

    int row = tid >> 2, cq = tid & 3;    // 64 rows x 4 col-quads
    float a0 = 0.f, a1 = 0.f, a2 = 0.f, a3 = 0.f;
#pragma unroll 8
    for (int k = 0; k < 128; k++) {
        float a = sA[row][k];
        float4 wv = *(float4*)&sW[k][cq * 4];
        a0 += a * wv.x; a1 += a * wv.y; a2 += a * wv.z; a3 += a * wv.w;
    }
    int gr = row0 + row;
    if (gr < nrows)
        *(float4*)(g_h2 + (size_t)gr * NCLS + cq * 4) = make_float4(a0, a1, a2, a3);
}

// ---------------- gather2: out[i] = b2 + dinv_i^2*h2[i] + sum_j nrm_j*h2[row_j]  (4 thr/node) ----------------
__global__ __launch_bounds__(256) void gather2_kernel(
    const float* __restrict__ b2, float* __restrict__ out, int n)
{
    int t = blockIdx.x * 256 + threadIdx.x;
    int i = t >> 2, q = t & 3;
    if (i >= n) return;
    int start = g_off[i], end = g_off[i + 1];
    float di = g_dinv[i];
    float s  = di * di;

    float4 hv = ((const float4*)(g_h2 + (size_t)i * NCLS))[q];
    float4 bb = ((const float4*)b2)[q];
    float4 acc0 = make_float4(bb.x + s * hv.x, bb.y + s * hv.y,
                              bb.z + s * hv.z, bb.w + s * hv.w);
    float4 acc1 = make_float4(0.f, 0.f, 0.f, 0.f);

    int j = start;
    for (; j + 2 <= end; j += 2) {
        int2 e0 = g_csr[j], e1 = g_csr[j + 1];
        float4 v0 = ((const float4*)(g_h2 + (size_t)e0.x * NCLS))[q];
        float4 v1 = ((const float4*)(g_h2 + (size_t)e1.x * NCLS))[q];
        float n0 = __int_as_float(e0.y), n1 = __int_as_float(e1.y);
        acc0.x += n0 * v0.x; acc0.y += n0 * v0.y; acc0.z += n0 * v0.z; acc0.w += n0 * v0.w;
        acc1.x += n1 * v1.x; acc1.y += n1 * v1.y; acc1.z += n1 * v1.z; acc1.w += n1 * v1.w;
    }
    if (j < end) {
        int2 e0 = g_csr[j];
        float4 v0 = ((const float4*)(g_h2 + (size_t)e0.x * NCLS))[q];
        float n0 = __int_as_float(e0.y);
        acc0.x += n0 * v0.x; acc0.y += n0 * v0.y; acc0.z += n0 * v0.z; acc0.w += n0 * v0.w;
    }
    ((float4*)(out + (size_t)i * NCLS))[q] =
        make_float4(acc0.x + acc1.x, acc0.y + acc1.y, acc0.z + acc1.z, acc0.w + acc1.w);
}

// ---------------- launch ----------------
extern "C" void kernel_launch(void* const* d_in, const int* in_sizes, int n_in,
                              void* d_out, int out_size)
{
    const void*  ei  = d_in[0];                 // edge_index [2, E] (int32 or int64)
    const float* ew  = (const float*)d_in[1];   // edge_weight [E]
    const float* emb = (const float*)d_in[2];   // [N, 128]
    const float* W1  = (const float*)d_in[3];   // [128, 128]
    const float* b1  = (const float*)d_in[4];   // [128]
    const float* W2  = (const float*)d_in[5];   // [128, 16]
    const float* b2  = (const float*)d_in[6];   // [16]
    float* out = (float*)d_out;

    int E = in_sizes[0] / 2;
    int N = in_sizes[2] / HIDDEN;

    detect_kernel<<<1, 32>>>(ei, in_sizes[0], N);
    init_kernel<<<(N + 255) / 256, 256>>>(N);
    degcnt_kernel<<<(E + 255) / 256, 256>>>(ei, ew, E);
    dinv_kernel<<<(N + 255) / 256, 256>>>(N);
    scan_kernel<<<1, 1024>>>(N);
    cursor_kernel<<<(N + 255) / 256, 256>>>(N);
    place_kernel<<<(E + 255) / 256, 256>>>(ei, ew, E);

    gemm1_kernel<<<(N + 63) / 64, 256>>>(emb, W1, N);

    long long t1 = (long long)N * 32;
    gather1_kernel<<<(unsigned)((t1 + 255) / 256), 256>>>(b1, N);

    gemm2_kernel<<<(N + 63) / 64, 256>>>(W2, N);

    long long t2 = (long long)N * 4;
    gather2_kernel<<<(unsigned)((t2 + 255) / 256), 256>>>(b2, out, N);
}

// round 15
// speedup vs baseline: 1.2465x; 1.2465x over previous
#include <cuda_runtime.h>
#include <cuda_fp16.h>
#include <cstdint>

#define HIDDEN 128
#define NCLS 16
#define MAXN 100000
#define MAXE 3200000
#define NBLK_MAX 512

// ---------------- device scratch (no allocations allowed) ----------------
__device__ float2 g_degcnt[MAXN];         // (weighted degree incl self, in-count)
__device__ float  g_dinv[MAXN];
__device__ int    g_off [MAXN + 1];       // CSR offsets
__device__ int    g_cur [MAXN];           // placement cursors
__device__ int    g_blksum[NBLK_MAX];     // scan block partials
__device__ int2   g_csr [MAXE];           // (src row, norm-bits) per edge, grouped by dst
__device__ __half g_h1h[(size_t)MAXN * HIDDEN];  // emb @ W1, fp16
__device__ float  g_x1 [(size_t)MAXN * HIDDEN];  // layer-1 aggregated (pre-relu)
__device__ float  g_h2 [(size_t)MAXN * NCLS];    // relu(x1) @ W2
__device__ int    g_is64;

// ---------------- helpers ----------------
__device__ __forceinline__ long long load_idx(const void* ei, long long pos, int is64) {
    if (is64) return ((const long long*)ei)[pos];
    return (long long)((const int*)ei)[pos];
}

__device__ __forceinline__ unsigned long long pack2(float lo, float hi) {
    unsigned long long r;
    asm("mov.b64 %0, {%1, %2};" : "=l"(r) : "f"(lo), "f"(hi));
    return r;
}
__device__ __forceinline__ float2 unpack2(unsigned long long v) {
    float2 f;
    asm("mov.b64 {%0, %1}, %2;" : "=f"(f.x), "=f"(f.y) : "l"(v));
    return f;
}
// d = a*b + d   (packed 2x fp32, sm_100+; ptxas never emits this from C++)
__device__ __forceinline__ void fma2(unsigned long long& d, unsigned long long a, unsigned long long b) {
    asm("fma.rn.f32x2 %0, %1, %2, %0;" : "+l"(d) : "l"(a), "l"(b));
}

// ---------------- dtype detection ----------------
__global__ void detect_kernel(const void* ei, int twoE, int nrows) {
    if (blockIdx.x == 0 && threadIdx.x == 0) {
        const long long* p = (const long long*)ei;
        int n = twoE / 2;
        if (n > 64) n = 64;
        int is64 = 1;
        for (int i = 0; i < n; i++) {
            long long v = p[i];
            if (v < 0 || v >= (long long)nrows) { is64 = 0; break; }
        }
        g_is64 = is64;
    }
}

// ---------------- init: deg=1 (self loop), cnt=0 ----------------
__global__ void init_kernel(int n) {
    int i = blockIdx.x * blockDim.x + threadIdx.x;
    if (i < n) g_degcnt[i] = make_float2(1.0f, 0.0f);
}

// ---------------- degree (weighted) + in-count, one vector red ----------------
__global__ void degcnt_kernel(const void* __restrict__ ei, const float* __restrict__ ew, int E) {
    int is64 = g_is64;
    int e = blockIdx.x * blockDim.x + threadIdx.x;
    if (e >= E) return;
    int c = (int)load_idx(ei, (long long)E + e, is64);
    float w = __ldg(ew + e);
    asm volatile("red.global.add.v2.f32 [%0], {%1, %2};"
                 :: "l"(&g_degcnt[c]), "f"(w), "f"(1.0f) : "memory");
}

// ---------------- scan_a: block-local exclusive scan of counts; also computes dinv ----------------
__global__ __launch_bounds__(256) void scan_a(int n) {
    __shared__ int wsum[8], woff[8];
    int b = blockIdx.x, tid = threadIdx.x, lane = tid & 31, w = tid >> 5;
    int i = b * 256 + tid;
    float2 dc = (i < n) ? g_degcnt[i] : make_float2(1.0f, 0.0f);
    if (i < n) g_dinv[i] = (dc.x > 0.0f) ? rsqrtf(dc.x) : 0.0f;
    int v = (i < n) ? (int)dc.y : 0;
    int sc = v;
#pragma unroll
    for (int d = 1; d < 32; d <<= 1) {
        int t = __shfl_up_sync(0xFFFFFFFFu, sc, d);
        if (lane >= d) sc += t;
    }
    if (lane == 31) wsum[w] = sc;
    __syncthreads();
    if (tid == 0) {
        int s = 0;
#pragma unroll
        for (int j = 0; j < 8; j++) { woff[j] = s; s += wsum[j]; }
        g_blksum[b] = s;
    }
    __syncthreads();
    if (i < n) g_off[i] = woff[w] + sc - v;
}

__global__ __launch_bounds__(512) void scan_b(int nblk, int n) {
    __shared__ int wsum[16], woff[16];
    int tid = threadIdx.x, lane = tid & 31, w = tid >> 5;
    int v = (tid < nblk) ? g_blksum[tid] : 0;
    int sc = v;
#pragma unroll
    for (int d = 1; d < 32; d <<= 1) {
        int t = __shfl_up_sync(0xFFFFFFFFu, sc, d);
        if (lane >= d) sc += t;
    }
    if (lane == 31) wsum[w] = sc;
    __syncthreads();
    if (tid == 0) {
        int s = 0;
#pragma unroll
        for (int j = 0; j < 16; j++) { woff[j] = s; s += wsum[j]; }
        g_off[n] = s;
    }
    __syncthreads();
    if (tid < nblk) g_blksum[tid] = woff[w] + sc - v;
}

__global__ void scan_c(int n) {
    int i = blockIdx.x * blockDim.x + threadIdx.x;
    if (i < n) {
        int off = g_off[i] + g_blksum[i >> 8];
        g_off[i] = off;
        g_cur[i] = off;
    }
}

// ---------------- CSR placement: record (row, norm) grouped by col ----------------
__global__ void place_kernel(const void* __restrict__ ei, const float* __restrict__ ew, int E) {
    int is64 = g_is64;
    int e = blockIdx.x * blockDim.x + threadIdx.x;
    if (e >= E) return;
    int r = (int)load_idx(ei, e, is64);
    int c = (int)load_idx(ei, (long long)E + e, is64);
    float nrm = g_dinv[r] * __ldg(ew + e) * g_dinv[c];
    int pos = atomicAdd(&g_cur[c], 1);
    g_csr[pos] = make_int2(r, __float_as_int(nrm));
}

// ---------------- GEMM1: h1 = emb @ W1 -> fp16, packed f32x2 FMA (K=32 tiles, 32KB smem) ----------------
__global__ __launch_bounds__(256) void gemm1_kernel(
    const float* __restrict__ emb, const float* __restrict__ W1, int nrows)
{
    __shared__ unsigned long long sA2[64][32];  // duplicated-pair A: 16 KB
    __shared__ float sW[32][128];               // 16 KB
    int tid  = threadIdx.x;
    int warp = tid >> 5, lane = tid & 31;
    int row0 = blockIdx.x * 64;

    unsigned long long acc2[8][2];
#pragma unroll
    for (int r = 0; r < 8; r++) { acc2[r][0] = 0ull; acc2[r][1] = 0ull; }

    for (int kt = 0; kt < HIDDEN; kt += 32) {
        __syncthreads();
        // stage A tile (duplicated pairs): 64 rows x 32 k = 512 float4
#pragma unroll
        for (int i = 0; i < 2; i++) {
            int idx = tid + i * 256;          // 0..511
            int r = idx >> 3, c4 = idx & 7;
            int gr = row0 + r;
            float4 v = make_float4(0.f, 0.f, 0.f, 0.f);
            if (gr < nrows)
                v = *(const float4*)(emb + (size_t)gr * HIDDEN + kt + c4 * 4);
            sA2[r][c4 * 4 + 0] = pack2(v.x, v.x);
            sA2[r][c4 * 4 + 1] = pack2(v.y, v.y);
            sA2[r][c4 * 4 + 2] = pack2(v.z, v.z);
            sA2[r][c4 * 4 + 3] = pack2(v.w, v.w);
        }
        // stage W tile: 32 k x 128 = 1024 float4
#pragma unroll
        for (int i = 0; i < 4; i++) {
            int idx = tid + i * 256;          // 0..1023
            int k = idx >> 5, c4 = idx & 31;
            *(float4*)&sW[k][c4 * 4] =
                *(const float4*)(W1 + (size_t)(kt + k) * HIDDEN + c4 * 4);
        }
        __syncthreads();
#pragma unroll 4
        for (int k = 0; k < 32; k++) {
            ulonglong2 wp = *(const ulonglong2*)&sW[k][lane * 4];  // cols {0,1},{2,3}
#pragma unroll
            for (int r = 0; r < 8; r++) {
                unsigned long long ad = sA2[warp * 8 + r][k];      // broadcast LDS.64
                fma2(acc2[r][0], ad, wp.x);
                fma2(acc2[r][1], ad, wp.y);
            }
        }
    }
#pragma unroll
    for (int r = 0; r < 8; r++) {
        int gr = row0 + warp * 8 + r;
        if (gr < nrows) {
            float2 p01 = unpack2(acc2[r][0]);
            float2 p23 = unpack2(acc2[r][1]);
            __half2 h01 = __floats2half2_rn(p01.x, p01.y);
            __half2 h23 = __floats2half2_rn(p23.x, p23.y);
            uint2 u;
            u.x = *(unsigned int*)&h01;
            u.y = *(unsigned int*)&h23;
            ((uint2*)(g_h1h + (size_t)gr * HIDDEN))[lane] = u;
        }
    }
}

// ---------------- gather1: x1[i] = b1 + dinv_i^2*h1[i] + sum_j nrm_j*h1[row_j]
//                  1 warp/node, unroll-4, record-prefetch software pipeline ----------------
__global__ __launch_bounds__(256) void gather1_kernel(const float* __restrict__ b1, int n)
{
    int gw   = (blockIdx.x * 256 + threadIdx.x) >> 5;
    int lane = threadIdx.x & 31;
    if (gw >= n) return;
    int start = g_off[gw], end = g_off[gw + 1];
    float di = g_dinv[gw];
    float s  = di * di;

    uint2 us = ((const uint2*)(g_h1h + (size_t)gw * HIDDEN))[lane];
    float2 s01 = __half22float2(*(__half2*)&us.x);
    float2 s23 = __half22float2(*(__half2*)&us.y);
    float4 bb = ((const float4*)b1)[lane];
    float4 acc0 = make_float4(bb.x + s * s01.x, bb.y + s * s01.y,
                              bb.z + s * s23.x, bb.w + s * s23.y);
    float4 acc1 = make_float4(0.f, 0.f, 0.f, 0.f);
    float4 acc2 = make_float4(0.f, 0.f, 0.f, 0.f);
    float4 acc3 = make_float4(0.f, 0.f, 0.f, 0.f);

    int j = start;
    int2 e0, e1, e2, e3;
    if (j + 4 <= end) {
        e0 = g_csr[j]; e1 = g_csr[j + 1]; e2 = g_csr[j + 2]; e3 = g_csr[j + 3];
    }
    // pipelined loop: prefetch next quad of records before consuming current gathers
    for (; j + 8 <= end; j += 4) {
        int2 f0 = g_csr[j + 4], f1 = g_csr[j + 5], f2 = g_csr[j + 6], f3 = g_csr[j + 7];
        uint2 u0 = ((const uint2*)(g_h1h + (size_t)e0.x * HIDDEN))[lane];
        uint2 u1 = ((const uint2*)(g_h1h + (size_t)e1.x * HIDDEN))[lane];
        uint2 u2 = ((const uint2*)(g_h1h + (size_t)e2.x * HIDDEN))[lane];
        uint2 u3 = ((const uint2*)(g_h1h + (size_t)e3.x * HIDDEN))[lane];
        float n0 = __int_as_float(e0.y), n1 = __int_as_float(e1.y);
        float n2 = __int_as_float(e2.y), n3 = __int_as_float(e3.y);
        float2 a01, a23;
        a01 = __half22float2(*(__half2*)&u0.x); a23 = __half22float2(*(__half2*)&u0.y);
        acc0.x += n0 * a01.x; acc0.y += n0 * a01.y; acc0.z += n0 * a23.x; acc0.w += n0 * a23.y;
        a01 = __half22float2(*(__half2*)&u1.x); a23 = __half22float2(*(__half2*)&u1.y);
        acc1.x += n1 * a01.x; acc1.y += n1 * a01.y; acc1.z += n1 * a23.x; acc1.w += n1 * a23.y;
        a01 = __half22float2(*(__half2*)&u2.x); a23 = __half22float2(*(__half2*)&u2.y);
        acc2.x += n2 * a01.x; acc2.y += n2 * a01.y; acc2.z += n2 * a23.x; acc2.w += n2 * a23.y;
        a01 = __half22float2(*(__half2*)&u3.x); a23 = __half22float2(*(__half2*)&u3.y);
        acc3.x += n3 * a01.x; acc3.y += n3 * a01.y; acc3.z += n3 * a23.x; acc3.w += n3 * a23.y;
        e0 = f0; e1 = f1; e2 = f2; e3 = f3;
    }
    // drain the last full quad held in registers
    if (j + 4 <= end) {
        uint2 u0 = ((const uint2*)(g_h1h + (size_t)e0.x * HIDDEN))[lane];
        uint2 u1 = ((const uint2*)(g_h1h + (size_t)e1.x * HIDDEN))[lane];
        uint2 u2 = ((const uint2*)(g_h1h + (size_t)e2.x * HIDDEN))[lane];
        uint2 u3 = ((const uint2*)(g_h1h + (size_t)e3.x * HIDDEN))[lane];
        float n0 = __int_as_float(e0.y), n1 = __int_as_float(e1.y);
        float n2 = __int_as_float(e2.y), n3 = __int_as_float(e3.y);
        float2 a01, a23;
        a01 = __half22float2(*(__half2*)&u0.x); a23 = __half22float2(*(__half2*)&u0.y);
        acc0.x += n0 * a01.x; acc0.y += n0 * a01.y; acc0.z += n0 * a23.x; acc0.w += n0 * a23.y;
        a01 = __half22float2(*(__half2*)&u1.x); a23 = __half22float2(*(__half2*)&u1.y);
        acc1.x += n1 * a01.x; acc1.y += n1 * a01.y; acc1.z += n1 * a23.x; acc1.w += n1 * a23.y;
        a01 = __half22float2(*(__half2*)&u2.x); a23 = __half22float2(*(__half2*)&u2.y);
        acc2.x += n2 * a01.x; acc2.y += n2 * a01.y; acc2.z += n2 * a23.x; acc2.w += n2 * a23.y;
        a01 = __half22float2(*(__half2*)&u3.x); a23 = __half22float2(*(__half2*)&u3.y);
        acc3.x += n3 * a01.x; acc3.y += n3 * a01.y; acc3.z += n3 * a23.x; acc3.w += n3 * a23.y;
        j += 4;
    }
    for (; j < end; j++) {
        int2 e = g_csr[j];
        uint2 u0 = ((const uint2*)(g_h1h + (size_t)e.x * HIDDEN))[lane];
        float n0 = __int_as_float(e.y);
        float2 a01 = __half22float2(*(__half2*)&u0.x);
        float2 a23 = __half22float2(*(__half2*)&u0.y);
        acc0.x += n0 * a01.x; acc0.y += n0 * a01.y; acc0.z += n0 * a23.x; acc0.w += n0 * a23.y;
    }
    ((float4*)(g_x1 + (size_t)gw * HIDDEN))[lane] =
        make_float4(acc0.x + acc1.x + acc2.x + acc3.x,
                    acc0.y + acc1.y + acc2.y + acc3.y,
                    acc0.z + acc1.z + acc2.z + acc3.z,
                    acc0.w + acc1.w + acc2.w + acc3.w);
}

// ---------------- GEMM2: h2 = relu(x1) @ W2, packed f32x2 ----------------
__global__ __launch_bounds__(256) void gemm2_kernel(const float* __restrict__ W2, int nrows)
{
    __shared__ float sA[64][132];    // padded: conflict-free row access (~33KB)
    __shared__ float sW[128][16];    // 8KB
    int tid  = threadIdx.x;
    int row0 = blockIdx.x * 64;

#pragma unroll
    for (int i = 0; i < 2; i++) {
        int idx = tid + i * 256;
        *(float4*)((float*)sW + idx * 4) = *(const float4*)(W2 + idx * 4);
    }
#pragma unroll
    for (int i = 0; i < 8; i++) {
        int idx = tid + i * 256;          // 0..2047
        int r = idx >> 5, c4 = idx & 31;
        int gr = row0 + r;
        float4 v = make_float4(0.f, 0.f, 0.f, 0.f);
        if (gr < nrows)
            v = *(const float4*)(g_x1 + (size_t)gr * HIDDEN + c4 * 4);
        v.x = fmaxf(v.x, 0.f); v.y = fmaxf(v.y, 0.f);
        v.z = fmaxf(v.z, 0.f); v.w = fmaxf(v.w, 0.f);
        *(float4*)&sA[r][c4 * 4] = v;
    }
    __syncthreads();

    int row = tid >> 2, cq = tid & 3;    // 64 rows x 4 col-quads
    unsigned long long acc01 = 0ull, acc23 = 0ull;
#pragma unroll 8
    for (int k = 0; k < 128; k++) {
        float a = sA[row][k];
        unsigned long long ad = pack2(a, a);
        ulonglong2 wp = *(const ulonglong2*)&sW[k][cq * 4];
        fma2(acc01, ad, wp.x);
        fma2(acc23, ad, wp.y);
    }
    int gr = row0 + row;
    if (gr < nrows) {
        float2 p01 = unpack2(acc01), p23 = unpack2(acc23);
        *(float4*)(g_h2 + (size_t)gr * NCLS + cq * 4) =
            make_float4(p01.x, p01.y, p23.x, p23.y);
    }
}

// ---------------- gather2: out[i] = b2 + dinv_i^2*h2[i] + sum_j nrm_j*h2[row_j]
//                  4 thr/node, unroll-4, record-prefetch pipeline ----------------
__global__ __launch_bounds__(256) void gather2_kernel(
    const float* __restrict__ b2, float* __restrict__ out, int n)
{
    int t = blockIdx.x * 256 + threadIdx.x;
    int i = t >> 2, q = t & 3;
    if (i >= n) return;
    int start = g_off[i], end = g_off[i + 1];
    float di = g_dinv[i];
    float s  = di * di;

    float4 hv = ((const float4*)(g_h2 + (size_t)i * NCLS))[q];
    float4 bb = ((const float4*)b2)[q];
    float4 acc0 = make_float4(bb.x + s * hv.x, bb.y + s * hv.y,
                              bb.z + s * hv.z, bb.w + s * hv.w);
    float4 acc1 = make_float4(0.f, 0.f, 0.f, 0.f);
    float4 acc2 = make_float4(0.f, 0.f, 0.f, 0.f);
    float4 acc3 = make_float4(0.f, 0.f, 0.f, 0.f);

    int j = start;
    int2 e0, e1, e2, e3;
    if (j + 4 <= end) {
        e0 = g_csr[j]; e1 = g_csr[j + 1]; e2 = g_csr[j + 2]; e3 = g_csr[j + 3];
    }
    for (; j + 8 <= end; j += 4) {
        int2 f0 = g_csr[j + 4], f1 = g_csr[j + 5], f2 = g_csr[j + 6], f3 = g_csr[j + 7];
        float4 v0 = ((const float4*)(g_h2 + (size_t)e0.x * NCLS))[q];
        float4 v1 = ((const float4*)(g_h2 + (size_t)e1.x * NCLS))[q];
        float4 v2 = ((const float4*)(g_h2 + (size_t)e2.x * NCLS))[q];
        float4 v3 = ((const float4*)(g_h2 + (size_t)e3.x * NCLS))[q];
        float n0 = __int_as_float(e0.y), n1 = __int_as_float(e1.y);
        float n2 = __int_as_float(e2.y), n3 = __int_as_float(e3.y);
        acc0.x += n0 * v0.x; acc0.y += n0 * v0.y; acc0.z += n0 * v0.z; acc0.w += n0 * v0.w;
        acc1.x += n1 * v1.x; acc1.y += n1 * v1.y; acc1.z += n1 * v1.z; acc1.w += n1 * v1.w;
        acc2.x += n2 * v2.x; acc2.y += n2 * v2.y; acc2.z += n2 * v2.z; acc2.w += n2 * v2.w;
        acc3.x += n3 * v3.x; acc3.y += n3 * v3.y; acc3.z += n3 * v3.z; acc3.w += n3 * v3.w;
        e0 = f0; e1 = f1; e2 = f2; e3 = f3;
    }
    if (j + 4 <= end) {
        float4 v0 = ((const float4*)(g_h2 + (size_t)e0.x * NCLS))[q];
        float4 v1 = ((const float4*)(g_h2 + (size_t)e1.x * NCLS))[q];
        float4 v2 = ((const float4*)(g_h2 + (size_t)e2.x * NCLS))[q];
        float4 v3 = ((const float4*)(g_h2 + (size_t)e3.x * NCLS))[q];
        float n0 = __int_as_float(e0.y), n1 = __int_as_float(e1.y);
        float n2 = __int_as_float(e2.y), n3 = __int_as_float(e3.y);
        acc0.x += n0 * v0.x; acc0.y += n0 * v0.y; acc0.z += n0 * v0.z; acc0.w += n0 * v0.w;
        acc1.x += n1 * v1.x; acc1.y += n1 * v1.y; acc1.z += n1 * v1.z; acc1.w += n1 * v1.w;
        acc2.x += n2 * v2.x; acc2.y += n2 * v2.y; acc2.z += n2 * v2.z; acc2.w += n2 * v2.w;
        acc3.x += n3 * v3.x; acc3.y += n3 * v3.y; acc3.z += n3 * v3.z; acc3.w += n3 * v3.w;
        j += 4;
    }
    for (; j < end; j++) {
        int2 e = g_csr[j];
        float4 v0 = ((const float4*)(g_h2 + (size_t)e.x * NCLS))[q];
        float n0 = __int_as_float(e.y);
        acc0.x += n0 * v0.x; acc0.y += n0 * v0.y; acc0.z += n0 * v0.z; acc0.w += n0 * v0.w;
    }
    ((float4*)(out + (size_t)i * NCLS))[q] =
        make_float4(acc0.x + acc1.x + acc2.x + acc3.x,
                    acc0.y + acc1.y + acc2.y + acc3.y,
                    acc0.z + acc1.z + acc2.z + acc3.z,
                    acc0.w + acc1.w + acc2.w + acc3.w);
}

// ---------------- launch ----------------
extern "C" void kernel_launch(void* const* d_in, const int* in_sizes, int n_in,
                              void* d_out, int out_size)
{
    const void*  ei  = d_in[0];                 // edge_index [2, E]
    const float* ew  = (const float*)d_in[1];   // edge_weight [E]
    const float* emb = (const float*)d_in[2];   // [N, 128]
    const float* W1  = (const float*)d_in[3];   // [128, 128]
    const float* b1  = (const float*)d_in[4];   // [128]
    const float* W2  = (const float*)d_in[5];   // [128, 16]
    const float* b2  = (const float*)d_in[6];   // [16]
    float* out = (float*)d_out;

    int E = in_sizes[0] / 2;
    int N = in_sizes[2] / HIDDEN;
    int nblk = (N + 255) / 256;

    detect_kernel<<<1, 32>>>(ei, in_sizes[0], N);
    init_kernel<<<(N + 255) / 256, 256>>>(N);
    degcnt_kernel<<<(E + 255) / 256, 256>>>(ei, ew, E);
    scan_a<<<nblk, 256>>>(N);
    scan_b<<<1, 512>>>(nblk, N);
    scan_c<<<nblk, 256>>>(N);
    place_kernel<<<(E + 255) / 256, 256>>>(ei, ew, E);

    gemm1_kernel<<<(N + 63) / 64, 256>>>(emb, W1, N);

    long long t1 = (long long)N * 32;
    gather1_kernel<<<(unsigned)((t1 + 255) / 256), 256>>>(b1, N);

    gemm2_kernel<<<(N + 63) / 64, 256>>>(W2, N);

    long long t2 = (long long)N * 4;
    gather2_kernel<<<(unsigned)((t2 + 255) / 256), 256>>>(b2, out, N);
}